// round 5
// baseline (speedup 1.0000x reference)
#include <cuda_runtime.h>
#include <cuda_bf16.h>

#define THREADS 256
#define NBLK    1184          // 148 SMs * 8 blocks
#define NWARP   (THREADS / 32)
#define MAXB    64
#define CAP     (1 << 23)     // zseg capacity (33.5 MB static)

// ---------------- device scratch (no allocations allowed) ----------------
__device__ unsigned d_gmax[MAXB * NBLK];
__device__ unsigned d_pmin[MAXB * NBLK];
__device__ unsigned d_zmin[MAXB * NBLK];
__device__ unsigned d_zmax[MAXB * NBLK];
__device__ float    d_part[NBLK];
__device__ float    d_mu[MAXB];
__device__ unsigned d_c1;
__device__ unsigned d_c2;
__device__ float    g_zseg[CAP];     // z with segment bit packed in mantissa LSB

// order-preserving float <-> uint
__device__ __forceinline__ unsigned ordf(float f) {
    unsigned u = __float_as_uint(f);
    return (u & 0x80000000u) ? ~u : (u | 0x80000000u);
}
__device__ __forceinline__ float deordf(unsigned o) {
    unsigned u = (o & 0x80000000u) ? (o & 0x7FFFFFFFu) : ~o;
    return __uint_as_float(u);
}
__device__ __forceinline__ float frcp(float x) {
    float r; asm("rcp.approx.f32 %0, %1;" : "=f"(r) : "f"(x)); return r;
}
__device__ __forceinline__ float packzs(float z, int s) {
    return __uint_as_float((__float_as_uint(z) & ~1u) | (unsigned)(s & 1));
}

// ================= kernel 1: per-cloud z reductions + zseg + mu =================
template <bool WZ>
__global__ void __launch_bounds__(THREADS) k_pass1(
    const float4* __restrict__ coord4, const int4* __restrict__ seg4,
    const float*  __restrict__ coord,  const int*  __restrict__ segment,
    const int* __restrict__ offset, int n, int B, int gpb)
{
    __shared__ unsigned s_gmax[MAXB], s_pmin[MAXB], s_zmin[MAXB], s_zmax[MAXB];
    __shared__ int s_off[MAXB];
    __shared__ unsigned s_rg[NWARP], s_rp[NWARP], s_rm[NWARP], s_rx[NWARP];
    __shared__ bool s_last;

    int t = threadIdx.x;
    int bid = blockIdx.x;
    int lane = t & 31, warp = t >> 5;

    for (int j = t; j < B; j += THREADS) {
        s_gmax[j] = 0u;  s_pmin[j] = ~0u;
        s_zmin[j] = ~0u; s_zmax[j] = 0u;
        s_off[j]  = offset[j];
    }
    __syncthreads();

    int n4 = n >> 2;
    int g0 = bid * gpb;
    int g1 = min(g0 + gpb, n4);
    bool isLast = (bid == (int)gridDim.x - 1);
    int tail0 = n4 << 2;
    bool hasWork = (g0 < g1) || (isLast && tail0 < n);

    if (hasWork) {
        int p0 = min(g0 << 2, n - 1);
        int pe = isLast ? (n - 1) : ((g1 << 2) - 1);
        int b0 = 0; while (p0 >= s_off[b0]) b0++;
        int b1 = b0; while (pe >= s_off[b1]) b1++;

        if (b0 == b1) {
            // ---- fast path: block fully inside one batch; pure streaming ----
            unsigned lzm = ~0u, lzx = 0u, lg = 0u, lp = ~0u;
            int g = g0 + t;
            for (; g + THREADS < g1; g += 2 * THREADS) {
                int h = g + THREADS;
                // front-batch all 8 loads
                float4 a0 = __ldcs(coord4 + 3 * g + 0);
                float4 b0v= __ldcs(coord4 + 3 * g + 1);
                float4 c0 = __ldcs(coord4 + 3 * g + 2);
                int4   s0 = __ldcs(seg4 + g);
                float4 a1 = __ldcs(coord4 + 3 * h + 0);
                float4 b1v= __ldcs(coord4 + 3 * h + 1);
                float4 c1 = __ldcs(coord4 + 3 * h + 2);
                int4   s1 = __ldcs(seg4 + h);

                unsigned o0 = ordf(a0.z), o1 = ordf(b0v.y), o2 = ordf(c0.x), o3 = ordf(c0.w);
                unsigned q0 = ordf(a1.z), q1 = ordf(b1v.y), q2 = ordf(c1.x), q3 = ordf(c1.w);
                lzm = min(lzm, min(min(o0, o1), min(o2, o3)));
                lzm = min(lzm, min(min(q0, q1), min(q2, q3)));
                lzx = max(lzx, max(max(o0, o1), max(o2, o3)));
                lzx = max(lzx, max(max(q0, q1), max(q2, q3)));
                lg  = max(lg, max(max(s0.x ? 0u : o0, s0.y ? 0u : o1),
                                  max(s0.z ? 0u : o2, s0.w ? 0u : o3)));
                lg  = max(lg, max(max(s1.x ? 0u : q0, s1.y ? 0u : q1),
                                  max(s1.z ? 0u : q2, s1.w ? 0u : q3)));
                lp  = min(lp, min(min(s0.x ? o0 : ~0u, s0.y ? o1 : ~0u),
                                  min(s0.z ? o2 : ~0u, s0.w ? o3 : ~0u)));
                lp  = min(lp, min(min(s1.x ? q0 : ~0u, s1.y ? q1 : ~0u),
                                  min(s1.z ? q2 : ~0u, s1.w ? q3 : ~0u)));
                if (WZ) {
                    float4 z0 = make_float4(packzs(a0.z, s0.x), packzs(b0v.y, s0.y),
                                            packzs(c0.x, s0.z), packzs(c0.w, s0.w));
                    float4 z1 = make_float4(packzs(a1.z, s1.x), packzs(b1v.y, s1.y),
                                            packzs(c1.x, s1.z), packzs(c1.w, s1.w));
                    *reinterpret_cast<float4*>(g_zseg + (g << 2)) = z0;
                    *reinterpret_cast<float4*>(g_zseg + (h << 2)) = z1;
                }
            }
            if (g < g1) {
                float4 a  = __ldcs(coord4 + 3 * g + 0);
                float4 bb = __ldcs(coord4 + 3 * g + 1);
                float4 c  = __ldcs(coord4 + 3 * g + 2);
                int4   s  = __ldcs(seg4 + g);
                unsigned o0 = ordf(a.z), o1 = ordf(bb.y), o2 = ordf(c.x), o3 = ordf(c.w);
                lzm = min(lzm, min(min(o0, o1), min(o2, o3)));
                lzx = max(lzx, max(max(o0, o1), max(o2, o3)));
                lg  = max(lg, max(max(s.x ? 0u : o0, s.y ? 0u : o1),
                                  max(s.z ? 0u : o2, s.w ? 0u : o3)));
                lp  = min(lp, min(min(s.x ? o0 : ~0u, s.y ? o1 : ~0u),
                                  min(s.z ? o2 : ~0u, s.w ? o3 : ~0u)));
                if (WZ) {
                    float4 z0 = make_float4(packzs(a.z, s.x), packzs(bb.y, s.y),
                                            packzs(c.x, s.z), packzs(c.w, s.w));
                    *reinterpret_cast<float4*>(g_zseg + (g << 2)) = z0;
                }
            }
            if (isLast) {
                for (int i = tail0 + t; i < n; i += THREADS) {
                    float z = coord[3 * i + 2];
                    int sv = segment[i];
                    unsigned o = ordf(z);
                    if (sv) lp = min(lp, o); else lg = max(lg, o);
                    lzm = min(lzm, o); lzx = max(lzx, o);
                    if (WZ) g_zseg[i] = packzs(z, sv);
                }
            }
            #pragma unroll
            for (int o = 16; o > 0; o >>= 1) {
                lzm = min(lzm, __shfl_xor_sync(~0u, lzm, o));
                lzx = max(lzx, __shfl_xor_sync(~0u, lzx, o));
                lg  = max(lg,  __shfl_xor_sync(~0u, lg,  o));
                lp  = min(lp,  __shfl_xor_sync(~0u, lp,  o));
            }
            if (lane == 0) {
                atomicMin(&s_zmin[b0], lzm);
                atomicMax(&s_zmax[b0], lzx);
                atomicMax(&s_gmax[b0], lg);
                atomicMin(&s_pmin[b0], lp);
            }
        } else {
            // ---- slow path (<=B-1 straddle blocks): per-warp uniformity ----
            int wbase = t & ~31;
            for (int gw = g0 + wbase; gw < g1; gw += THREADS) {
                int g = gw + lane;
                bool act = (g < g1);
                int wp0 = gw << 2;
                int wpe = (min(gw + 32, g1) << 2) - 1;
                int c0 = 0; while (wp0 >= s_off[c0]) c0++;
                int c1 = c0; while (wpe >= s_off[c1]) c1++;

                float4 a, bb, c; int4 s;
                if (act) {
                    a = coord4[3 * g + 0]; bb = coord4[3 * g + 1];
                    c = coord4[3 * g + 2]; s = seg4[g];
                    if (WZ) {
                        float4 z0 = make_float4(packzs(a.z, s.x), packzs(bb.y, s.y),
                                                packzs(c.x, s.z), packzs(c.w, s.w));
                        *reinterpret_cast<float4*>(g_zseg + (g << 2)) = z0;
                    }
                }
                if (c0 == c1) {
                    unsigned lzm = ~0u, lzx = 0u, lg = 0u, lp = ~0u;
                    if (act) {
                        unsigned o0 = ordf(a.z), o1 = ordf(bb.y), o2 = ordf(c.x), o3 = ordf(c.w);
                        lzm = min(min(o0, o1), min(o2, o3));
                        lzx = max(max(o0, o1), max(o2, o3));
                        lg  = max(max(s.x ? 0u : o0, s.y ? 0u : o1),
                                  max(s.z ? 0u : o2, s.w ? 0u : o3));
                        lp  = min(min(s.x ? o0 : ~0u, s.y ? o1 : ~0u),
                                  min(s.z ? o2 : ~0u, s.w ? o3 : ~0u));
                    }
                    #pragma unroll
                    for (int o = 16; o > 0; o >>= 1) {
                        lzm = min(lzm, __shfl_xor_sync(~0u, lzm, o));
                        lzx = max(lzx, __shfl_xor_sync(~0u, lzx, o));
                        lg  = max(lg,  __shfl_xor_sync(~0u, lg,  o));
                        lp  = min(lp,  __shfl_xor_sync(~0u, lp,  o));
                    }
                    if (lane == 0) {
                        atomicMin(&s_zmin[c0], lzm);
                        atomicMax(&s_zmax[c0], lzx);
                        atomicMax(&s_gmax[c0], lg);
                        atomicMin(&s_pmin[c0], lp);
                    }
                } else if (act) {
                    int i0 = g << 2;
                    float zz[4] = {a.z, bb.y, c.x, c.w};
                    int   ss[4] = {s.x, s.y, s.z, s.w};
                    int b = c0;
                    #pragma unroll
                    for (int q = 0; q < 4; q++) {
                        int i = i0 + q;
                        while (i >= s_off[b]) b++;
                        unsigned o = ordf(zz[q]);
                        atomicMin(&s_zmin[b], o);
                        atomicMax(&s_zmax[b], o);
                        if (ss[q]) atomicMin(&s_pmin[b], o);
                        else       atomicMax(&s_gmax[b], o);
                    }
                }
            }
            if (isLast) {
                for (int i = tail0 + t; i < n; i += THREADS) {
                    int b = 0; while (i >= s_off[b]) b++;
                    float z = coord[3 * i + 2];
                    int sv = segment[i];
                    unsigned o = ordf(z);
                    atomicMin(&s_zmin[b], o);
                    atomicMax(&s_zmax[b], o);
                    if (sv) atomicMin(&s_pmin[b], o);
                    else    atomicMax(&s_gmax[b], o);
                    if (WZ) g_zseg[i] = packzs(z, sv);
                }
            }
        }
    }

    __syncthreads();
    for (int j = t; j < B; j += THREADS) {
        d_gmax[j * NBLK + bid] = s_gmax[j];
        d_pmin[j * NBLK + bid] = s_pmin[j];
        d_zmin[j * NBLK + bid] = s_zmin[j];
        d_zmax[j * NBLK + bid] = s_zmax[j];
    }
    __threadfence();
    if (t == 0) s_last = (atomicAdd(&d_c1, 1u) == gridDim.x - 1);
    __syncthreads();

    if (s_last) {
        for (int j = 0; j < B; j++) {
            unsigned gm = 0u, pm = ~0u, zm = ~0u, zx = 0u;
            for (int r = t; r < (int)gridDim.x; r += THREADS) {
                gm = max(gm, d_gmax[j * NBLK + r]);
                pm = min(pm, d_pmin[j * NBLK + r]);
                zm = min(zm, d_zmin[j * NBLK + r]);
                zx = max(zx, d_zmax[j * NBLK + r]);
            }
            #pragma unroll
            for (int o = 16; o > 0; o >>= 1) {
                gm = max(gm, __shfl_xor_sync(~0u, gm, o));
                pm = min(pm, __shfl_xor_sync(~0u, pm, o));
                zm = min(zm, __shfl_xor_sync(~0u, zm, o));
                zx = max(zx, __shfl_xor_sync(~0u, zx, o));
            }
            if (lane == 0) { s_rg[warp] = gm; s_rp[warp] = pm; s_rm[warp] = zm; s_rx[warp] = zx; }
            __syncthreads();
            if (t == 0) {
                gm = s_rg[0]; pm = s_rp[0]; zm = s_rm[0]; zx = s_rx[0];
                #pragma unroll
                for (int w = 1; w < NWARP; w++) {
                    gm = max(gm, s_rg[w]); pm = min(pm, s_rp[w]);
                    zm = min(zm, s_rm[w]); zx = max(zx, s_rx[w]);
                }
                float g = (gm != 0u)  ? deordf(gm) : deordf(zm);
                float p = (pm != ~0u) ? deordf(pm) : deordf(zx);
                d_mu[j] = g + (p - g) * 0.5f;
            }
            __syncthreads();
        }
        if (t == 0) d_c1 = 0u;
    }
}

// ================= kernel 2: focal-CE * gaussian, reduce + finalize =================
__device__ __forceinline__ float pointTermZ(float p0, float p1, float z, float mu)
{
    int s = __float_as_uint(z) & 1;
    float tgt = s ? p1 : p0;
    float oth = s ? p0 : p1;
    float v   = oth - tgt;
    float e   = __expf(-fabsf(v));
    float inv = frcp(1.0f + e);
    float sig = (v >= 0.0f ? 1.0f : e) * inv;       // 1 - p_t
    float sp  = fmaxf(v, 0.0f) + __logf(1.0f + e);  // -log p_t
    float d   = z - mu;
    float dd  = d * d;
    float cf  = (d <= 0.0f) ? -50.0f : -3.125f;
    float w   = __expf(cf * dd);
    if (d > 0.8f) w = 0.1f;
    return sp * sig * sig * w;
}
__device__ __forceinline__ float pointTerm(float p0, float p1, int s, float z, float mu)
{
    return pointTermZ(p0, p1, packzs(z, s), mu);
}

template <bool USEZ>
__global__ void __launch_bounds__(THREADS) k_loss(
    const float4* __restrict__ pred4, const float* __restrict__ pred,
    const float4* __restrict__ coord4, const float* __restrict__ coord,
    const int4* __restrict__ seg4, const int* __restrict__ segment,
    const int* __restrict__ offset, int n, int B, int gpb, float* __restrict__ out)
{
    __shared__ int    s_off[MAXB];
    __shared__ float  s_mu[MAXB];
    __shared__ float  s_w[NWARP];
    __shared__ bool   s_last;
    __shared__ double s_d[THREADS];

    int t = threadIdx.x;
    int bid = blockIdx.x;
    for (int j = t; j < B; j += THREADS) {
        s_off[j] = offset[j];
        s_mu[j]  = d_mu[j];
    }
    __syncthreads();

    int n4 = n >> 2;
    int g0 = bid * gpb;
    int g1 = min(g0 + gpb, n4);
    bool isLast = (bid == (int)gridDim.x - 1);
    int tail0 = n4 << 2;

    float acc = 0.0f;

    if (g0 < g1) {
        int p0 = g0 << 2;
        int pe = isLast ? (n - 1) : ((g1 << 2) - 1);
        int b0 = 0; while (p0 >= s_off[b0]) b0++;
        int b1 = b0; while (pe >= s_off[b1]) b1++;
        bool uni = (b0 == b1);
        float muu = s_mu[b0];
        int curb = b0;

        auto muOf = [&](int g, float& m0, float& m1, float& m2, float& m3) {
            if (uni) { m0 = m1 = m2 = m3 = muu; return; }
            int i0 = g << 2;
            while (i0 >= s_off[curb]) curb++;
            int q1 = curb; while (i0 + 1 >= s_off[q1]) q1++;
            int q2 = q1;   while (i0 + 2 >= s_off[q2]) q2++;
            int q3 = q2;   while (i0 + 3 >= s_off[q3]) q3++;
            m0 = s_mu[curb]; m1 = s_mu[q1]; m2 = s_mu[q2]; m3 = s_mu[q3];
        };

        int g = g0 + t;
        if (USEZ) {
            for (; g + THREADS < g1; g += 2 * THREADS) {
                int h = g + THREADS;
                float4 pa0 = __ldcs(pred4 + 2 * g + 0);
                float4 pb0 = __ldcs(pred4 + 2 * g + 1);
                float4 zs0 = *reinterpret_cast<const float4*>(g_zseg + (g << 2));
                float4 pa1 = __ldcs(pred4 + 2 * h + 0);
                float4 pb1 = __ldcs(pred4 + 2 * h + 1);
                float4 zs1 = *reinterpret_cast<const float4*>(g_zseg + (h << 2));
                float m0, m1, m2, m3;
                muOf(g, m0, m1, m2, m3);
                acc += pointTermZ(pa0.x, pa0.y, zs0.x, m0);
                acc += pointTermZ(pa0.z, pa0.w, zs0.y, m1);
                acc += pointTermZ(pb0.x, pb0.y, zs0.z, m2);
                acc += pointTermZ(pb0.z, pb0.w, zs0.w, m3);
                muOf(h, m0, m1, m2, m3);
                acc += pointTermZ(pa1.x, pa1.y, zs1.x, m0);
                acc += pointTermZ(pa1.z, pa1.w, zs1.y, m1);
                acc += pointTermZ(pb1.x, pb1.y, zs1.z, m2);
                acc += pointTermZ(pb1.z, pb1.w, zs1.w, m3);
            }
            if (g < g1) {
                float4 pa = __ldcs(pred4 + 2 * g + 0);
                float4 pb = __ldcs(pred4 + 2 * g + 1);
                float4 zs = *reinterpret_cast<const float4*>(g_zseg + (g << 2));
                float m0, m1, m2, m3;
                muOf(g, m0, m1, m2, m3);
                acc += pointTermZ(pa.x, pa.y, zs.x, m0);
                acc += pointTermZ(pa.z, pa.w, zs.y, m1);
                acc += pointTermZ(pb.x, pb.y, zs.z, m2);
                acc += pointTermZ(pb.z, pb.w, zs.w, m3);
            }
        } else {
            for (; g < g1; g += THREADS) {
                float4 pa = __ldcs(pred4 + 2 * g + 0);
                float4 pb = __ldcs(pred4 + 2 * g + 1);
                float4 a  = __ldcs(coord4 + 3 * g + 0);
                float4 bb = __ldcs(coord4 + 3 * g + 1);
                float4 c  = __ldcs(coord4 + 3 * g + 2);
                int4   s  = __ldcs(seg4 + g);
                float m0, m1, m2, m3;
                muOf(g, m0, m1, m2, m3);
                acc += pointTerm(pa.x, pa.y, s.x, a.z,  m0);
                acc += pointTerm(pa.z, pa.w, s.y, bb.y, m1);
                acc += pointTerm(pb.x, pb.y, s.z, c.x,  m2);
                acc += pointTerm(pb.z, pb.w, s.w, c.w,  m3);
            }
        }
    }

    if (isLast && t < (n - tail0)) {
        int i = tail0 + t;
        int b = 0; while (i >= s_off[b]) b++;
        if (USEZ) {
            acc += pointTermZ(pred[2 * i], pred[2 * i + 1], g_zseg[i], s_mu[b]);
        } else {
            acc += pointTerm(pred[2 * i], pred[2 * i + 1], segment[i],
                             coord[3 * i + 2], s_mu[b]);
        }
    }

    // block reduce
    #pragma unroll
    for (int o = 16; o > 0; o >>= 1) acc += __shfl_xor_sync(~0u, acc, o);
    int warp = t >> 5, lane = t & 31;
    if (lane == 0) s_w[warp] = acc;
    __syncthreads();
    if (t == 0) {
        float tot = 0.0f;
        #pragma unroll
        for (int w = 0; w < NWARP; w++) tot += s_w[w];
        d_part[bid] = tot;
        __threadfence();
        s_last = (atomicAdd(&d_c2, 1u) == gridDim.x - 1);
    }
    __syncthreads();

    if (s_last) {
        double da = 0.0;
        for (int i = t; i < (int)gridDim.x; i += THREADS) da += (double)d_part[i];
        s_d[t] = da;
        __syncthreads();
        for (int s = THREADS / 2; s > 0; s >>= 1) {
            if (t < s) s_d[t] += s_d[t + s];
            __syncthreads();
        }
        if (t == 0) { out[0] = (float)(s_d[0] / (double)n); d_c2 = 0u; }
    }
}

// ---------------- launch ----------------
extern "C" void kernel_launch(void* const* d_in, const int* in_sizes, int n_in,
                              void* d_out, int out_size)
{
    const float* pred    = (const float*)d_in[0];
    const float* coord   = (const float*)d_in[1];
    const int*   segment = (const int*)d_in[2];
    const int*   offset  = (const int*)d_in[3];
    int n = in_sizes[2];
    int B = in_sizes[3];
    if (B > MAXB) B = MAXB;
    if (B < 1) B = 1;

    int n4 = n >> 2;
    int gpb = (n4 + NBLK - 1) / NBLK;
    if (gpb < 1) gpb = 1;
    bool useZ = (n <= CAP);

    if (useZ) {
        k_pass1<true><<<NBLK, THREADS>>>((const float4*)coord, (const int4*)segment,
                                         coord, segment, offset, n, B, gpb);
        k_loss<true><<<NBLK, THREADS>>>((const float4*)pred, pred,
                                        (const float4*)coord, coord,
                                        (const int4*)segment, segment,
                                        offset, n, B, gpb, (float*)d_out);
    } else {
        k_pass1<false><<<NBLK, THREADS>>>((const float4*)coord, (const int4*)segment,
                                          coord, segment, offset, n, B, gpb);
        k_loss<false><<<NBLK, THREADS>>>((const float4*)pred, pred,
                                         (const float4*)coord, coord,
                                         (const int4*)segment, segment,
                                         offset, n, B, gpb, (float*)d_out);
    }
}

// round 6
// speedup vs baseline: 1.1678x; 1.1678x over previous
#include <cuda_runtime.h>
#include <cuda_bf16.h>

#define THREADS 256
#define NB      592            // 148 SMs * 4 co-resident blocks (full single wave)
#define NWARP   (THREADS / 32)
#define MAXB    64
#define GCAP    1792           // groups (of 4 pts) cached in smem per block: 28672 B

// ---------------- device scratch (zero-init; no allocations) ----------------
__device__ unsigned d_gmax[MAXB * NB];
__device__ unsigned d_pmin[MAXB * NB];
__device__ unsigned d_zmin[MAXB * NB];
__device__ unsigned d_zmax[MAXB * NB];
__device__ float    d_part[NB];
__device__ float    d_mu[MAXB];
__device__ unsigned d_c1;      // phase-A arrival counter
__device__ unsigned d_c2;      // phase-B arrival counter
__device__ unsigned d_flag;    // mu-ready flag

__device__ __forceinline__ unsigned ordf(float f) {
    unsigned u = __float_as_uint(f);
    return (u & 0x80000000u) ? ~u : (u | 0x80000000u);
}
__device__ __forceinline__ float deordf(unsigned o) {
    unsigned u = (o & 0x80000000u) ? (o & 0x7FFFFFFFu) : ~o;
    return __uint_as_float(u);
}
__device__ __forceinline__ float frcp(float x) {
    float r; asm("rcp.approx.f32 %0, %1;" : "=f"(r) : "f"(x)); return r;
}
__device__ __forceinline__ float packzs(float z, int s) {
    return __uint_as_float((__float_as_uint(z) & ~1u) | (unsigned)(s & 1));
}

// focal-CE * gaussian weight; segment bit lives in z's mantissa LSB
__device__ __forceinline__ float pointTermZ(float p0, float p1, float z, float mu)
{
    int s = __float_as_uint(z) & 1;
    float tgt = s ? p1 : p0;
    float oth = s ? p0 : p1;
    float v   = oth - tgt;
    float e   = __expf(-fabsf(v));
    float inv = frcp(1.0f + e);
    float sig = (v >= 0.0f ? 1.0f : e) * inv;        // 1 - p_t
    float sp  = fmaxf(v, 0.0f) + __logf(1.0f + e);   // -log p_t
    float d   = z - mu;
    float dd  = d * d;
    float cf  = (d <= 0.0f) ? -50.0f : -3.125f;      // 1/(2*.1^2), 1/(2*.4^2)
    float w   = __expf(cf * dd);
    if (d > 0.8f) w = 0.1f;                          // clamp past 2*SIGMA_R
    return sp * sig * sig * w;
}

// ================= single fused persistent kernel =================
template <bool SMEMZ>
__global__ void __launch_bounds__(THREADS, 4) k_fused(
    const float4* __restrict__ pred4, const float* __restrict__ pred,
    const float4* __restrict__ coord4, const float* __restrict__ coord,
    const int4* __restrict__ seg4, const int* __restrict__ segment,
    const int* __restrict__ offset, int n, int B, int gpb, float* __restrict__ out)
{
    __shared__ float    s_z[GCAP * 4];            // 28672 B packed z+seg
    __shared__ int      s_off[MAXB];
    __shared__ float    s_mu[MAXB];
    __shared__ unsigned s_g[MAXB], s_p[MAXB], s_m[MAXB], s_x[MAXB];
    __shared__ unsigned s_rg[NWARP], s_rp[NWARP], s_rm[NWARP], s_rx[NWARP];
    __shared__ float    s_w[NWARP];
    __shared__ bool     s_last;

    int t = threadIdx.x;
    int bid = blockIdx.x;
    int lane = t & 31, warp = t >> 5;

    for (int j = t; j < B; j += THREADS) {
        s_g[j] = 0u;  s_p[j] = ~0u;
        s_m[j] = ~0u; s_x[j] = 0u;
        s_off[j] = offset[j];
    }
    __syncthreads();

    int n4 = n >> 2;
    int g0 = bid * gpb;
    int g1 = min(g0 + gpb, n4);
    bool isLast = (bid == NB - 1);
    int tail0 = n4 << 2;
    bool hasWork = (g0 < g1) || (isLast && tail0 < n);

    int b0 = 0, b1 = 0;
    bool uni = true;

    // ===================== phase A: z reductions (+ stage z in smem) =====================
    if (hasWork) {
        int p0 = min(g0 << 2, n - 1);
        int pe = isLast ? (n - 1) : ((g1 << 2) - 1);
        while (p0 >= s_off[b0]) b0++;
        b1 = b0; while (pe >= s_off[b1]) b1++;
        uni = (b0 == b1);

        if (uni) {
            unsigned lzm = ~0u, lzx = 0u, lg = 0u, lp = ~0u;
            for (int g = g0 + t; g < g1; g += THREADS) {
                float4 a  = coord4[3 * g + 0];
                float4 bb = coord4[3 * g + 1];
                float4 c  = coord4[3 * g + 2];
                int4   s  = seg4[g];
                unsigned o0 = ordf(a.z), o1 = ordf(bb.y), o2 = ordf(c.x), o3 = ordf(c.w);
                lzm = min(lzm, min(min(o0, o1), min(o2, o3)));
                lzx = max(lzx, max(max(o0, o1), max(o2, o3)));
                lg  = max(lg, max(max(s.x ? 0u : o0, s.y ? 0u : o1),
                                  max(s.z ? 0u : o2, s.w ? 0u : o3)));
                lp  = min(lp, min(min(s.x ? o0 : ~0u, s.y ? o1 : ~0u),
                                  min(s.z ? o2 : ~0u, s.w ? o3 : ~0u)));
                if (SMEMZ) {
                    float4 zv = make_float4(packzs(a.z, s.x), packzs(bb.y, s.y),
                                            packzs(c.x, s.z), packzs(c.w, s.w));
                    *reinterpret_cast<float4*>(s_z + ((g - g0) << 2)) = zv;
                }
            }
            if (isLast) {
                for (int i = tail0 + t; i < n; i += THREADS) {
                    unsigned o = ordf(coord[3 * i + 2]);
                    if (segment[i]) lp = min(lp, o); else lg = max(lg, o);
                    lzm = min(lzm, o); lzx = max(lzx, o);
                }
            }
            #pragma unroll
            for (int o = 16; o > 0; o >>= 1) {
                lzm = min(lzm, __shfl_xor_sync(~0u, lzm, o));
                lzx = max(lzx, __shfl_xor_sync(~0u, lzx, o));
                lg  = max(lg,  __shfl_xor_sync(~0u, lg,  o));
                lp  = min(lp,  __shfl_xor_sync(~0u, lp,  o));
            }
            if (lane == 0) {
                atomicMin(&s_m[b0], lzm);
                atomicMax(&s_x[b0], lzx);
                atomicMax(&s_g[b0], lg);
                atomicMin(&s_p[b0], lp);
            }
        } else {
            // straddle block (<= B-1 of them): per-warp uniformity
            int wbase = t & ~31;
            for (int gw = g0 + wbase; gw < g1; gw += THREADS) {
                int g = gw + lane;
                bool act = (g < g1);
                int wp0 = gw << 2;
                int wpe = (min(gw + 32, g1) << 2) - 1;
                int c0 = 0; while (wp0 >= s_off[c0]) c0++;
                int c1 = c0; while (wpe >= s_off[c1]) c1++;

                float4 a, bb, c; int4 s;
                if (act) {
                    a = coord4[3 * g + 0]; bb = coord4[3 * g + 1];
                    c = coord4[3 * g + 2]; s = seg4[g];
                    if (SMEMZ) {
                        float4 zv = make_float4(packzs(a.z, s.x), packzs(bb.y, s.y),
                                                packzs(c.x, s.z), packzs(c.w, s.w));
                        *reinterpret_cast<float4*>(s_z + ((g - g0) << 2)) = zv;
                    }
                }
                if (c0 == c1) {
                    unsigned lzm = ~0u, lzx = 0u, lg = 0u, lp = ~0u;
                    if (act) {
                        unsigned o0 = ordf(a.z), o1 = ordf(bb.y), o2 = ordf(c.x), o3 = ordf(c.w);
                        lzm = min(min(o0, o1), min(o2, o3));
                        lzx = max(max(o0, o1), max(o2, o3));
                        lg  = max(max(s.x ? 0u : o0, s.y ? 0u : o1),
                                  max(s.z ? 0u : o2, s.w ? 0u : o3));
                        lp  = min(min(s.x ? o0 : ~0u, s.y ? o1 : ~0u),
                                  min(s.z ? o2 : ~0u, s.w ? o3 : ~0u));
                    }
                    #pragma unroll
                    for (int o = 16; o > 0; o >>= 1) {
                        lzm = min(lzm, __shfl_xor_sync(~0u, lzm, o));
                        lzx = max(lzx, __shfl_xor_sync(~0u, lzx, o));
                        lg  = max(lg,  __shfl_xor_sync(~0u, lg,  o));
                        lp  = min(lp,  __shfl_xor_sync(~0u, lp,  o));
                    }
                    if (lane == 0) {
                        atomicMin(&s_m[c0], lzm);
                        atomicMax(&s_x[c0], lzx);
                        atomicMax(&s_g[c0], lg);
                        atomicMin(&s_p[c0], lp);
                    }
                } else if (act) {
                    int i0 = g << 2;
                    float zz[4] = {a.z, bb.y, c.x, c.w};
                    int   ss[4] = {s.x, s.y, s.z, s.w};
                    int b = c0;
                    #pragma unroll
                    for (int q = 0; q < 4; q++) {
                        int i = i0 + q;
                        while (i >= s_off[b]) b++;
                        unsigned o = ordf(zz[q]);
                        atomicMin(&s_m[b], o);
                        atomicMax(&s_x[b], o);
                        if (ss[q]) atomicMin(&s_p[b], o);
                        else       atomicMax(&s_g[b], o);
                    }
                }
            }
            if (isLast) {
                for (int i = tail0 + t; i < n; i += THREADS) {
                    int b = 0; while (i >= s_off[b]) b++;
                    unsigned o = ordf(coord[3 * i + 2]);
                    atomicMin(&s_m[b], o);
                    atomicMax(&s_x[b], o);
                    if (segment[i]) atomicMin(&s_p[b], o);
                    else            atomicMax(&s_g[b], o);
                }
            }
        }
    }

    __syncthreads();
    for (int j = t; j < B; j += THREADS) {
        d_gmax[j * NB + bid] = s_g[j];
        d_pmin[j * NB + bid] = s_p[j];
        d_zmin[j * NB + bid] = s_m[j];
        d_zmax[j * NB + bid] = s_x[j];
    }
    __threadfence();
    if (t == 0) s_last = (atomicAdd(&d_c1, 1u) == NB - 1);
    __syncthreads();

    // ===================== grid sync: last block computes mu =====================
    if (s_last) {
        for (int j = 0; j < B; j++) {
            unsigned gm = 0u, pm = ~0u, zm = ~0u, zx = 0u;
            for (int r = t; r < NB; r += THREADS) {
                gm = max(gm, d_gmax[j * NB + r]);
                pm = min(pm, d_pmin[j * NB + r]);
                zm = min(zm, d_zmin[j * NB + r]);
                zx = max(zx, d_zmax[j * NB + r]);
            }
            #pragma unroll
            for (int o = 16; o > 0; o >>= 1) {
                gm = max(gm, __shfl_xor_sync(~0u, gm, o));
                pm = min(pm, __shfl_xor_sync(~0u, pm, o));
                zm = min(zm, __shfl_xor_sync(~0u, zm, o));
                zx = max(zx, __shfl_xor_sync(~0u, zx, o));
            }
            if (lane == 0) { s_rg[warp] = gm; s_rp[warp] = pm; s_rm[warp] = zm; s_rx[warp] = zx; }
            __syncthreads();
            if (t == 0) {
                gm = s_rg[0]; pm = s_rp[0]; zm = s_rm[0]; zx = s_rx[0];
                #pragma unroll
                for (int w = 1; w < NWARP; w++) {
                    gm = max(gm, s_rg[w]); pm = min(pm, s_rp[w]);
                    zm = min(zm, s_rm[w]); zx = max(zx, s_rx[w]);
                }
                float g = (gm != 0u)  ? deordf(gm) : deordf(zm);
                float p = (pm != ~0u) ? deordf(pm) : deordf(zx);
                d_mu[j] = g + (p - g) * 0.5f;
            }
            __syncthreads();
        }
        if (t == 0) { __threadfence(); atomicExch(&d_flag, 1u); }
    } else if (t == 0) {
        while (atomicAdd(&d_flag, 0u) == 0u) { __nanosleep(64); }
    }
    __syncthreads();
    __threadfence();
    for (int j = t; j < B; j += THREADS) s_mu[j] = d_mu[j];
    __syncthreads();

    // ===================== phase B: focal-CE * weight, reduce =====================
    float acc = 0.0f;
    if (g0 < g1) {
        float muu = s_mu[b0];
        int curb = b0;
        for (int g = g0 + t; g < g1; g += THREADS) {
            float4 pa = pred4[2 * g + 0];
            float4 pb = pred4[2 * g + 1];
            float4 zs;
            if (SMEMZ) {
                zs = *reinterpret_cast<const float4*>(s_z + ((g - g0) << 2));
            } else {
                float4 a  = coord4[3 * g + 0];
                float4 bb = coord4[3 * g + 1];
                float4 c  = coord4[3 * g + 2];
                int4   s  = seg4[g];
                zs = make_float4(packzs(a.z, s.x), packzs(bb.y, s.y),
                                 packzs(c.x, s.z), packzs(c.w, s.w));
            }
            float m0 = muu, m1 = muu, m2 = muu, m3 = muu;
            if (!uni) {
                int i0 = g << 2;
                while (i0 >= s_off[curb]) curb++;
                int q1 = curb; while (i0 + 1 >= s_off[q1]) q1++;
                int q2 = q1;   while (i0 + 2 >= s_off[q2]) q2++;
                int q3 = q2;   while (i0 + 3 >= s_off[q3]) q3++;
                m0 = s_mu[curb]; m1 = s_mu[q1]; m2 = s_mu[q2]; m3 = s_mu[q3];
            }
            acc += pointTermZ(pa.x, pa.y, zs.x, m0);
            acc += pointTermZ(pa.z, pa.w, zs.y, m1);
            acc += pointTermZ(pb.x, pb.y, zs.z, m2);
            acc += pointTermZ(pb.z, pb.w, zs.w, m3);
        }
    }
    if (isLast && t < (n - tail0)) {
        int i = tail0 + t;
        int b = 0; while (i >= s_off[b]) b++;
        acc += pointTermZ(pred[2 * i], pred[2 * i + 1],
                          packzs(coord[3 * i + 2], segment[i]), s_mu[b]);
    }

    #pragma unroll
    for (int o = 16; o > 0; o >>= 1) acc += __shfl_xor_sync(~0u, acc, o);
    if (lane == 0) s_w[warp] = acc;
    __syncthreads();
    if (t == 0) {
        float tot = 0.0f;
        #pragma unroll
        for (int w = 0; w < NWARP; w++) tot += s_w[w];
        d_part[bid] = tot;
        __threadfence();
        s_last = (atomicAdd(&d_c2, 1u) == NB - 1);
    }
    __syncthreads();

    if (s_last) {
        __shared__ double s_d[THREADS];
        double da = 0.0;
        for (int i = t; i < NB; i += THREADS) da += (double)d_part[i];
        s_d[t] = da;
        __syncthreads();
        for (int s = THREADS / 2; s > 0; s >>= 1) {
            if (t < s) s_d[t] += s_d[t + s];
            __syncthreads();
        }
        if (t == 0) {
            out[0] = (float)(s_d[0] / (double)n);
            d_flag = 0u; d_c1 = 0u; d_c2 = 0u;   // reset for next graph replay
        }
    }
}

// ---------------- launch ----------------
extern "C" void kernel_launch(void* const* d_in, const int* in_sizes, int n_in,
                              void* d_out, int out_size)
{
    const float* pred    = (const float*)d_in[0];
    const float* coord   = (const float*)d_in[1];
    const int*   segment = (const int*)d_in[2];
    const int*   offset  = (const int*)d_in[3];
    int n = in_sizes[2];
    int B = in_sizes[3];
    if (B > MAXB) B = MAXB;
    if (B < 1) B = 1;

    int n4 = n >> 2;
    int gpb = (n4 + NB - 1) / NB;
    if (gpb < 1) gpb = 1;
    bool smemz = (gpb <= GCAP);

    if (smemz) {
        k_fused<true><<<NB, THREADS>>>((const float4*)pred, pred,
                                       (const float4*)coord, coord,
                                       (const int4*)segment, segment,
                                       offset, n, B, gpb, (float*)d_out);
    } else {
        k_fused<false><<<NB, THREADS>>>((const float4*)pred, pred,
                                        (const float4*)coord, coord,
                                        (const int4*)segment, segment,
                                        offset, n, B, gpb, (float*)d_out);
    }
}

// round 7
// speedup vs baseline: 1.5344x; 1.3138x over previous
#include <cuda_runtime.h>
#include <cuda_bf16.h>

#define THREADS 256
#define BPSM    6
#define NB      (148 * BPSM)      // 888 blocks, all co-resident (GB300 has 152 SMs)
#define NWARP   (THREADS / 32)
#define MAXB    64
#define GCAP    1184              // groups (4 pts) staged in smem: 18944 B

// ---------------- device scratch (zero-init; no allocations) ----------------
// All four stats stored as atomicMax-of-transformed (identity 0 == zero-init):
//   d_ag : max ord(z) over seg==0        (gmax;  0 => no ground points)
//   d_ap : max ~ord(z) over seg==1       (pmin = ~value; 0 => no plant points)
//   d_azm: max ~ord(z) over all          (zmin = ~value)
//   d_azx: max ord(z) over all           (zmax)
__device__ unsigned d_ag[MAXB];
__device__ unsigned d_ap[MAXB];
__device__ unsigned d_azm[MAXB];
__device__ unsigned d_azx[MAXB];
__device__ float    d_part[NB];
__device__ unsigned d_c1;      // phase-A arrival counter
__device__ unsigned d_c2;      // phase-B arrival counter

__device__ __forceinline__ unsigned ordf(float f) {
    unsigned u = __float_as_uint(f);
    return (u & 0x80000000u) ? ~u : (u | 0x80000000u);
}
__device__ __forceinline__ float deordf(unsigned o) {
    unsigned u = (o & 0x80000000u) ? (o & 0x7FFFFFFFu) : ~o;
    return __uint_as_float(u);
}
__device__ __forceinline__ float packzs(float z, int s) {
    return __uint_as_float((__float_as_uint(z) & ~1u) | (unsigned)(s & 1));
}

// focal-CE * gaussian weight; segment bit in z's mantissa LSB. 3 MUFU total.
__device__ __forceinline__ float pointTermZ(float p0, float p1, float z, float mu)
{
    int s = __float_as_uint(z) & 1;
    float tgt = s ? p1 : p0;
    float oth = s ? p0 : p1;
    float v   = oth - tgt;
    float nav = fminf(v, -v);                         // -|v|
    float e;  asm("ex2.approx.f32 %0,%1;" : "=f"(e)  : "f"(1.4426950409f * nav));
    float l2; asm("lg2.approx.f32 %0,%1;" : "=f"(l2) : "f"(1.0f + e));
    float sp = fmaxf(v, 0.0f) + 0.69314718056f * l2;  // -log p_t (softplus)
    float d  = z - mu;
    float dd = d * d;
    // log2 of gaussian weight: 1.442695*(-50) and 1.442695*(-3.125); clamp -> log2(0.1)
    float cf = (d <= 0.0f) ? -72.13475204f : -4.50842200f;
    float ew = (d > 0.8f) ? -3.32192809f : cf * dd;
    // sig^2 * w = ex2( 2*log2(sigmoid(v)) + ew ), log2 sig = 1.442695*min(v,0) - l2
    float ex = fmaf(2.8853900818f, fminf(v, 0.0f), fmaf(-2.0f, l2, ew));
    float sgw; asm("ex2.approx.f32 %0,%1;" : "=f"(sgw) : "f"(ex));
    return sp * sgw;
}

// ================= single fused persistent kernel =================
template <bool SMEMZ>
__global__ void __launch_bounds__(THREADS, BPSM) k_fused(
    const float4* __restrict__ pred4, const float* __restrict__ pred,
    const float4* __restrict__ coord4, const float* __restrict__ coord,
    const int4* __restrict__ seg4, const int* __restrict__ segment,
    const int* __restrict__ offset, int n, int B, int gpb, float* __restrict__ out)
{
    __shared__ float    s_z[GCAP * 4];        // 18944 B packed z+seg
    __shared__ int      s_off[MAXB];
    __shared__ float    s_mu[MAXB];
    __shared__ unsigned s_g[MAXB], s_p[MAXB], s_m[MAXB], s_x[MAXB];
    __shared__ float    s_w[NWARP];
    __shared__ bool     s_last;

    int t = threadIdx.x;
    int bid = blockIdx.x;
    int lane = t & 31, warp = t >> 5;

    for (int j = t; j < B; j += THREADS) {
        s_g[j] = 0u; s_p[j] = 0u; s_m[j] = 0u; s_x[j] = 0u;
        s_off[j] = offset[j];
    }
    __syncthreads();

    int n4 = n >> 2;
    int g0 = bid * gpb;
    int g1 = min(g0 + gpb, n4);
    bool isLast = (bid == NB - 1);
    int tail0 = n4 << 2;
    bool hasWork = (g0 < g1) || (isLast && tail0 < n);

    int b0 = 0, b1 = 0;
    bool uni = true;

    // ===================== phase A: z reductions (+ stage z in smem) =====================
    if (hasWork) {
        int p0 = min(g0 << 2, n - 1);
        int pe = isLast ? (n - 1) : ((g1 << 2) - 1);
        while (p0 >= s_off[b0]) b0++;
        b1 = b0; while (pe >= s_off[b1]) b1++;
        uni = (b0 == b1);

        if (uni) {
            unsigned lg = 0u, lp = 0u, lzm = 0u, lzx = 0u;   // all max, identity 0
            for (int g = g0 + t; g < g1; g += THREADS) {
                float4 a  = coord4[3 * g + 0];
                float4 bb = coord4[3 * g + 1];
                float4 c  = coord4[3 * g + 2];
                int4   s  = seg4[g];
                if (SMEMZ) {
                    float4 zv = make_float4(packzs(a.z, s.x), packzs(bb.y, s.y),
                                            packzs(c.x, s.z), packzs(c.w, s.w));
                    *reinterpret_cast<float4*>(s_z + ((g - g0) << 2)) = zv;
                }
                unsigned o0 = ordf(a.z), o1 = ordf(bb.y), o2 = ordf(c.x), o3 = ordf(c.w);
                lzx = max(lzx, max(max(o0, o1), max(o2, o3)));
                lzm = max(lzm, max(max(~o0, ~o1), max(~o2, ~o3)));
                lg  = max(lg, max(max(s.x ? 0u : o0, s.y ? 0u : o1),
                                  max(s.z ? 0u : o2, s.w ? 0u : o3)));
                lp  = max(lp, max(max(s.x ? ~o0 : 0u, s.y ? ~o1 : 0u),
                                  max(s.z ? ~o2 : 0u, s.w ? ~o3 : 0u)));
            }
            if (isLast) {
                for (int i = tail0 + t; i < n; i += THREADS) {
                    unsigned o = ordf(coord[3 * i + 2]);
                    if (segment[i]) lp = max(lp, ~o); else lg = max(lg, o);
                    lzm = max(lzm, ~o); lzx = max(lzx, o);
                }
            }
            #pragma unroll
            for (int o = 16; o > 0; o >>= 1) {
                lzm = max(lzm, __shfl_xor_sync(~0u, lzm, o));
                lzx = max(lzx, __shfl_xor_sync(~0u, lzx, o));
                lg  = max(lg,  __shfl_xor_sync(~0u, lg,  o));
                lp  = max(lp,  __shfl_xor_sync(~0u, lp,  o));
            }
            if (lane == 0) {
                atomicMax(&s_m[b0], lzm);
                atomicMax(&s_x[b0], lzx);
                atomicMax(&s_g[b0], lg);
                atomicMax(&s_p[b0], lp);
            }
        } else {
            // straddle block (<= B-1 of them): per-point smem atomics
            for (int g = g0 + t; g < g1; g += THREADS) {
                float4 a  = coord4[3 * g + 0];
                float4 bb = coord4[3 * g + 1];
                float4 c  = coord4[3 * g + 2];
                int4   s  = seg4[g];
                if (SMEMZ) {
                    float4 zv = make_float4(packzs(a.z, s.x), packzs(bb.y, s.y),
                                            packzs(c.x, s.z), packzs(c.w, s.w));
                    *reinterpret_cast<float4*>(s_z + ((g - g0) << 2)) = zv;
                }
                int i0 = g << 2;
                float zz[4] = {a.z, bb.y, c.x, c.w};
                int   ss[4] = {s.x, s.y, s.z, s.w};
                int b = b0;
                #pragma unroll
                for (int q = 0; q < 4; q++) {
                    int i = i0 + q;
                    while (i >= s_off[b]) b++;
                    unsigned o = ordf(zz[q]);
                    atomicMax(&s_m[b], ~o);
                    atomicMax(&s_x[b], o);
                    if (ss[q]) atomicMax(&s_p[b], ~o);
                    else       atomicMax(&s_g[b], o);
                }
            }
            if (isLast) {
                for (int i = tail0 + t; i < n; i += THREADS) {
                    int b = 0; while (i >= s_off[b]) b++;
                    unsigned o = ordf(coord[3 * i + 2]);
                    atomicMax(&s_m[b], ~o);
                    atomicMax(&s_x[b], o);
                    if (segment[i]) atomicMax(&s_p[b], ~o);
                    else            atomicMax(&s_g[b], o);
                }
            }
        }
    }

    __syncthreads();
    // block -> global: at most 4*B atomics per block, typically 4
    for (int j = t; j < B; j += THREADS) {
        if (s_g[j]) atomicMax(&d_ag[j],  s_g[j]);
        if (s_p[j]) atomicMax(&d_ap[j],  s_p[j]);
        if (s_m[j]) atomicMax(&d_azm[j], s_m[j]);
        if (s_x[j]) atomicMax(&d_azx[j], s_x[j]);
    }
    __threadfence();
    __syncthreads();
    if (t == 0) {
        atomicAdd(&d_c1, 1u);
        // spin until all blocks contributed
        while (*(volatile unsigned*)&d_c1 < (unsigned)NB) { __nanosleep(128); }
    }
    __syncthreads();
    __threadfence();

    // every block computes mu locally (32 L2 words)
    for (int j = t; j < B; j += THREADS) {
        unsigned ag  = __ldcg(&d_ag[j]);
        unsigned ap  = __ldcg(&d_ap[j]);
        unsigned azm = __ldcg(&d_azm[j]);
        unsigned azx = __ldcg(&d_azx[j]);
        float g = ag ? deordf(ag)  : deordf(~azm);   // gmax else zmin
        float p = ap ? deordf(~ap) : deordf(azx);    // pmin else zmax
        s_mu[j] = g + (p - g) * 0.5f;
    }
    __syncthreads();

    // ===================== phase B: focal-CE * weight, reduce =====================
    float acc = 0.0f;
    if (g0 < g1) {
        float muu = s_mu[b0];
        for (int g = g0 + t; g < g1; g += THREADS) {
            float4 pa = pred4[2 * g + 0];
            float4 pb = pred4[2 * g + 1];
            float4 zs;
            if (SMEMZ) {
                zs = *reinterpret_cast<const float4*>(s_z + ((g - g0) << 2));
            } else {
                float4 a  = coord4[3 * g + 0];
                float4 bb = coord4[3 * g + 1];
                float4 c  = coord4[3 * g + 2];
                int4   s  = seg4[g];
                zs = make_float4(packzs(a.z, s.x), packzs(bb.y, s.y),
                                 packzs(c.x, s.z), packzs(c.w, s.w));
            }
            float m0 = muu, m1 = muu, m2 = muu, m3 = muu;
            if (!uni) {
                int i0 = g << 2;
                int b = b0; while (i0 >= s_off[b]) b++;
                int q1 = b;  while (i0 + 1 >= s_off[q1]) q1++;
                int q2 = q1; while (i0 + 2 >= s_off[q2]) q2++;
                int q3 = q2; while (i0 + 3 >= s_off[q3]) q3++;
                m0 = s_mu[b]; m1 = s_mu[q1]; m2 = s_mu[q2]; m3 = s_mu[q3];
            }
            acc += pointTermZ(pa.x, pa.y, zs.x, m0);
            acc += pointTermZ(pa.z, pa.w, zs.y, m1);
            acc += pointTermZ(pb.x, pb.y, zs.z, m2);
            acc += pointTermZ(pb.z, pb.w, zs.w, m3);
        }
    }
    if (isLast && t < (n - tail0)) {
        int i = tail0 + t;
        int b = 0; while (i >= s_off[b]) b++;
        acc += pointTermZ(pred[2 * i], pred[2 * i + 1],
                          packzs(coord[3 * i + 2], segment[i]), s_mu[b]);
    }

    #pragma unroll
    for (int o = 16; o > 0; o >>= 1) acc += __shfl_xor_sync(~0u, acc, o);
    if (lane == 0) s_w[warp] = acc;
    __syncthreads();
    if (t == 0) {
        float tot = 0.0f;
        #pragma unroll
        for (int w = 0; w < NWARP; w++) tot += s_w[w];
        d_part[bid] = tot;
        __threadfence();
        s_last = (atomicAdd(&d_c2, 1u) == NB - 1);
    }
    __syncthreads();

    if (s_last) {
        // reuse s_z as double scratch (phase B done everywhere)
        double* s_d = reinterpret_cast<double*>(s_z);
        double da = 0.0;
        for (int i = t; i < NB; i += THREADS) da += (double)d_part[i];
        s_d[t] = da;
        __syncthreads();
        for (int s = THREADS / 2; s > 0; s >>= 1) {
            if (t < s) s_d[t] += s_d[t + s];
            __syncthreads();
        }
        // reset everything for next graph replay
        for (int j = t; j < B; j += THREADS) {
            d_ag[j] = 0u; d_ap[j] = 0u; d_azm[j] = 0u; d_azx[j] = 0u;
        }
        if (t == 0) {
            out[0] = (float)(s_d[0] / (double)n);
            d_c1 = 0u; d_c2 = 0u;
        }
    }
}

// ---------------- launch ----------------
extern "C" void kernel_launch(void* const* d_in, const int* in_sizes, int n_in,
                              void* d_out, int out_size)
{
    const float* pred    = (const float*)d_in[0];
    const float* coord   = (const float*)d_in[1];
    const int*   segment = (const int*)d_in[2];
    const int*   offset  = (const int*)d_in[3];
    int n = in_sizes[2];
    int B = in_sizes[3];
    if (B > MAXB) B = MAXB;
    if (B < 1) B = 1;

    int n4 = n >> 2;
    int gpb = (n4 + NB - 1) / NB;
    if (gpb < 1) gpb = 1;
    bool smemz = (gpb <= GCAP);

    if (smemz) {
        k_fused<true><<<NB, THREADS>>>((const float4*)pred, pred,
                                       (const float4*)coord, coord,
                                       (const int4*)segment, segment,
                                       offset, n, B, gpb, (float*)d_out);
    } else {
        k_fused<false><<<NB, THREADS>>>((const float4*)pred, pred,
                                        (const float4*)coord, coord,
                                        (const int4*)segment, segment,
                                        offset, n, B, gpb, (float*)d_out);
    }
}